// round 1
// baseline (speedup 1.0000x reference)
#include <cuda_runtime.h>
#include <math.h>

#define B   32
#define LL  128
#define LR  128
#define D   512
#define M   64
#define A   128
#define OC  259   // 1+64 | 64 | 1+64 | 1+64

// ---- scratch (static device globals; no runtime allocation) ----
__device__ float g_algt[(B*LL + B*LR) * A];   // a_lt rows [0,4096) then a_rt rows
__device__ float g_att[B*LL*D];               // attentive context vectors
__device__ float g_invnrt[B*LR];
__device__ int   g_idx[B*LL];

// ============================================================================
// Kernel: a_lt = tanh(L@W1)*diag ; a_rt = tanh(R@W1).  X = [L;R] (8192 x 512).
// grid: 512 blocks x 16 rows, 256 threads.
// ============================================================================
__global__ void __launch_bounds__(256) k_algt(
    const float* __restrict__ Lr, const float* __restrict__ Rr,
    const float* __restrict__ W1, const float* __restrict__ diag)
{
    __shared__ float Xs[16][17];
    __shared__ float Ws[16][A];
    int row0 = blockIdx.x * 16;
    int t = threadIdx.x;
    int c  = t & 127;
    int rh = t >> 7;           // 0/1 -> rows rh*8..rh*8+7
    float acc[8];
    #pragma unroll
    for (int i = 0; i < 8; i++) acc[i] = 0.f;

    for (int kt = 0; kt < D; kt += 16) {
        #pragma unroll
        for (int i = 0; i < 8; i++) {          // 16x128 W1 tile
            int f = i * 256 + t;
            int k = f >> 7, a = f & 127;
            Ws[k][a] = W1[(kt + k) * A + a];
        }
        {                                      // 16x16 X tile
            int r = t >> 4, k = t & 15;
            int grow = row0 + r;
            const float* X = (grow < B*LL) ? (Lr + (size_t)grow * D)
                                           : (Rr + (size_t)(grow - B*LL) * D);
            Xs[r][k] = X[kt + k];
        }
        __syncthreads();
        #pragma unroll
        for (int k = 0; k < 16; k++) {
            float w = Ws[k][c];
            #pragma unroll
            for (int i = 0; i < 8; i++)
                acc[i] = fmaf(Xs[rh*8 + i][k], w, acc[i]);
        }
        __syncthreads();
    }
    #pragma unroll
    for (int i = 0; i < 8; i++) {
        int grow = row0 + rh*8 + i;
        float v = tanhf(acc[i]);
        if (grow < B*LL) v *= diag[c];
        g_algt[(size_t)grow * A + c] = v;
    }
}

// ============================================================================
// Kernel: attentive context.  Per block: (b, 16 l's).
// scores -> softmax -> att = P @ R  -> g_att
// ============================================================================
__global__ void __launch_bounds__(256) k_att(const float* __restrict__ Rr)
{
    __shared__ float alt[16][129];
    __shared__ float art[16][129];
    __shared__ float S[16][132];
    __shared__ __align__(16) float Rs[4 * 512];

    int b  = blockIdx.y;
    int l0 = blockIdx.x * 16;
    int t  = threadIdx.x;
    int li = t >> 4, rj = t & 15;

    #pragma unroll
    for (int i = 0; i < 8; i++) {
        int f = i * 256 + t;
        int r = f >> 7, a = f & 127;
        alt[r][a] = g_algt[(size_t)(b*LL + l0 + r) * A + a];
    }

    for (int rc = 0; rc < 8; rc++) {
        __syncthreads();
        #pragma unroll
        for (int i = 0; i < 8; i++) {
            int f = i * 256 + t;
            int r = f >> 7, a = f & 127;
            art[r][a] = g_algt[(size_t)(B*LL + b*LR + rc*16 + r) * A + a];
        }
        __syncthreads();
        float s = 0.f;
        #pragma unroll 4
        for (int a = 0; a < A; a++) s = fmaf(alt[li][a], art[rj][a], s);
        S[li][rc*16 + rj] = s;
    }
    __syncthreads();

    // softmax rows (8 warps x 2 rows)
    int w = t >> 5, lane = t & 31;
    for (int rr = w; rr < 16; rr += 8) {
        float m0 = -1e30f;
        #pragma unroll
        for (int s0 = 0; s0 < 4; s0++) m0 = fmaxf(m0, S[rr][lane + 32*s0]);
        #pragma unroll
        for (int off = 16; off; off >>= 1) m0 = fmaxf(m0, __shfl_xor_sync(0xffffffffu, m0, off));
        float e[4], sum = 0.f;
        #pragma unroll
        for (int s0 = 0; s0 < 4; s0++) { e[s0] = expf(S[rr][lane + 32*s0] - m0); sum += e[s0]; }
        #pragma unroll
        for (int off = 16; off; off >>= 1) sum += __shfl_xor_sync(0xffffffffu, sum, off);
        float inv = 1.f / sum;
        #pragma unroll
        for (int s0 = 0; s0 < 4; s0++) S[rr][lane + 32*s0] = e[s0] * inv;
    }

    // att = P @ R   (thread owns li, float4 columns dg+16j)
    float4 acc[8];
    #pragma unroll
    for (int j = 0; j < 8; j++) acc[j] = make_float4(0.f, 0.f, 0.f, 0.f);
    int dg = rj;
    for (int rc = 0; rc < 32; rc++) {
        __syncthreads();
        #pragma unroll
        for (int i = 0; i < 8; i++) {
            int f = i * 256 + t;
            int r4 = f >> 9, d = f & 511;
            Rs[r4*512 + d] = Rr[(size_t)(b*LR + rc*4 + r4) * D + d];
        }
        __syncthreads();
        #pragma unroll
        for (int r4 = 0; r4 < 4; r4++) {
            float p = S[li][rc*4 + r4];
            const float4* Rrow = (const float4*)(Rs + r4*512);
            #pragma unroll
            for (int j = 0; j < 8; j++) {
                float4 v = Rrow[dg + 16*j];
                acc[j].x = fmaf(p, v.x, acc[j].x);
                acc[j].y = fmaf(p, v.y, acc[j].y);
                acc[j].z = fmaf(p, v.z, acc[j].z);
                acc[j].w = fmaf(p, v.w, acc[j].w);
            }
        }
    }
    float4* out = (float4*)(g_att + (size_t)(b*LL + l0 + li) * D);
    #pragma unroll
    for (int j = 0; j < 8; j++) out[dg + 16*j] = acc[j];
}

// ============================================================================
// Kernel: inv right norms:  rsqrt(max(||R[b,r]||^2, eps))
// ============================================================================
__global__ void k_nrt(const float* __restrict__ Rr)
{
    int b = blockIdx.x, t = threadIdx.x, w = t >> 5, lane = t & 31;
    for (int r = w; r < LR; r += 8) {
        const float* row = Rr + (size_t)(b*LR + r) * D;
        float s = 0.f;
        #pragma unroll 4
        for (int i = lane; i < D; i += 32) s = fmaf(row[i], row[i], s);
        #pragma unroll
        for (int off = 16; off; off >>= 1) s += __shfl_xor_sync(0xffffffffu, s, off);
        if (!lane) g_invnrt[b*LR + r] = rsqrtf(fmaxf(s, 1e-6f));
    }
}

// ============================================================================
// Kernel: argmax_r cosine(L[l], R[r]) -> g_idx.  n_lt factor drops out.
// Per block: (b, 16 l's). thread = (li, rj).
// ============================================================================
__global__ void __launch_bounds__(256) k_idx(
    const float* __restrict__ Lr, const float* __restrict__ Rr)
{
    __shared__ __align__(16) float Ls[16 * 512];
    __shared__ float Rs[16 * 67];
    int b = blockIdx.y, l0 = blockIdx.x * 16, t = threadIdx.x;

    #pragma unroll
    for (int i = 0; i < 32; i++) {
        int f = i * 256 + t;
        int r = f >> 9, d = f & 511;
        Ls[r*512 + d] = Lr[(size_t)(b*LL + l0 + r) * D + d];
    }

    int li = t >> 4, rj = t & 15;
    float bestv = -1e30f; int bestr = 0;
    for (int rc = 0; rc < 8; rc++) {
        float acc = 0.f;
        for (int dc = 0; dc < 8; dc++) {
            __syncthreads();
            #pragma unroll
            for (int i = 0; i < 4; i++) {
                int f = i * 256 + t;
                int rr = f >> 6, dd = f & 63;
                Rs[rr*67 + dd] = Rr[(size_t)(b*LR + rc*16 + rr) * D + dc*64 + dd];
            }
            __syncthreads();
            #pragma unroll 8
            for (int k = 0; k < 64; k++)
                acc = fmaf(Ls[li*512 + dc*64 + k], Rs[rj*67 + k], acc);
        }
        float rel = acc * g_invnrt[b*LR + rc*16 + rj];
        int r = rc*16 + rj;
        if (rel > bestv) { bestv = rel; bestr = r; }
    }
    // reduce over rj within 16-lane groups; ties -> smaller r (JAX first-occurrence)
    #pragma unroll
    for (int off = 8; off; off >>= 1) {
        float ov = __shfl_down_sync(0xffffffffu, bestv, off, 16);
        int   oi = __shfl_down_sync(0xffffffffu, bestr, off, 16);
        if (ov > bestv || (ov == bestv && oi < bestr)) { bestv = ov; bestr = oi; }
    }
    if (rj == 0) g_idx[b*LL + l0 + li] = bestr;
}

// ============================================================================
// Kernel: generic multi-perspective match.  One block per (b,l), 256 threads.
// mode 0: att = concat(h_rt_fw,h_rt_bw)[b]   (broadcast over l)
// mode 1: att = g_att[b,l]
// mode 2: att = R[b, g_idx[b,l]]
// ============================================================================
__global__ void __launch_bounds__(256) k_mp(
    const float* __restrict__ Lr,
    const float* __restrict__ hfw, const float* __restrict__ hbw,
    const float* __restrict__ Kmat, float* __restrict__ out,
    int mode, int col0, const float* __restrict__ Rr)
{
    __shared__ float prod[512];
    __shared__ float wsum[8];
    int bl = blockIdx.x;                 // b*LL + l
    int b  = bl >> 7;
    int t  = threadIdx.x;
    const float* Lrow = Lr + (size_t)bl * D;

    float p0, p1;
    if (mode == 0) {
        p0 = Lrow[t]       * hfw[b*256 + t];
        p1 = Lrow[t + 256] * hbw[b*256 + t];
    } else if (mode == 1) {
        const float* att = g_att + (size_t)bl * D;
        p0 = Lrow[t] * att[t]; p1 = Lrow[t + 256] * att[t + 256];
    } else {
        const float* att = Rr + (size_t)(b*LR + g_idx[bl]) * D;
        p0 = Lrow[t] * att[t]; p1 = Lrow[t + 256] * att[t + 256];
    }
    prod[t] = p0; prod[t + 256] = p1;

    float s = p0 + p1;
    int w = t >> 5, lane = t & 31;
    #pragma unroll
    for (int off = 16; off; off >>= 1) s += __shfl_xor_sync(0xffffffffu, s, off);
    if (!lane) wsum[w] = s;
    __syncthreads();
    if (t == 0) {
        float c = 0.f;
        #pragma unroll
        for (int i = 0; i < 8; i++) c += wsum[i];
        out[(size_t)bl * OC + col0] = tanhf(c);
    }

    // each warp: 8 perspectives; cache its prod slice in registers
    float pl[16];
    #pragma unroll
    for (int s0 = 0; s0 < 16; s0++) pl[s0] = prod[lane + 32*s0];
    #pragma unroll
    for (int i = 0; i < 8; i++) {
        int m = w*8 + i;
        const float* kr = Kmat + (size_t)m * D;
        float acc = 0.f;
        #pragma unroll
        for (int s0 = 0; s0 < 16; s0++) acc = fmaf(pl[s0], kr[lane + 32*s0], acc);
        #pragma unroll
        for (int off = 16; off; off >>= 1) acc += __shfl_xor_sync(0xffffffffu, acc, off);
        if (!lane) out[(size_t)bl * OC + col0 + 1 + m] = tanhf(acc);
    }
}

// ============================================================================
// Kernel: max-pooling match.  Per block: (m, b) -> 128x128x512 SGEMM
//   C[r,l] = sum_d (R[b,r,d]*K_m[d]) * L[b,l,d];  out = tanh(max_r C[r,l]).
// 256 thr, 8x8 microtile, BK=16.
// ============================================================================
__global__ void __launch_bounds__(256) k_mpool(
    const float* __restrict__ Lr, const float* __restrict__ Rr,
    const float* __restrict__ Kmp, float* __restrict__ out)
{
    __shared__ float Kd[512];
    __shared__ __align__(16) float As[16 * 132];
    __shared__ __align__(16) float Bs[16 * 132];

    int m = blockIdx.x, b = blockIdx.y;
    int t = threadIdx.x;
    int tx = t & 15, ty = t >> 4;

    Kd[t]       = Kmp[(size_t)m * D + t];
    Kd[t + 256] = Kmp[(size_t)m * D + t + 256];

    float acc[8][8];
    #pragma unroll
    for (int i = 0; i < 8; i++)
        #pragma unroll
        for (int j = 0; j < 8; j++) acc[i][j] = 0.f;

    const float* Rb = Rr + (size_t)b * LR * D;
    const float* Lb = Lr + (size_t)b * LL * D;

    for (int d0 = 0; d0 < D; d0 += 16) {
        __syncthreads();
        #pragma unroll
        for (int i = 0; i < 2; i++) {
            int f = i * 256 + t;
            int row = f >> 2, dq = (f & 3) * 4;
            float4 rv = *(const float4*)(Rb + (size_t)row * D + d0 + dq);
            As[(dq + 0) * 132 + row] = rv.x * Kd[d0 + dq + 0];
            As[(dq + 1) * 132 + row] = rv.y * Kd[d0 + dq + 1];
            As[(dq + 2) * 132 + row] = rv.z * Kd[d0 + dq + 2];
            As[(dq + 3) * 132 + row] = rv.w * Kd[d0 + dq + 3];
            float4 lv = *(const float4*)(Lb + (size_t)row * D + d0 + dq);
            Bs[(dq + 0) * 132 + row] = lv.x;
            Bs[(dq + 1) * 132 + row] = lv.y;
            Bs[(dq + 2) * 132 + row] = lv.z;
            Bs[(dq + 3) * 132 + row] = lv.w;
        }
        __syncthreads();
        #pragma unroll
        for (int k = 0; k < 16; k++) {
            float4 a0 = *(const float4*)&As[k*132 + ty*8];
            float4 a1 = *(const float4*)&As[k*132 + ty*8 + 4];
            float4 b0 = *(const float4*)&Bs[k*132 + tx*8];
            float4 b1 = *(const float4*)&Bs[k*132 + tx*8 + 4];
            float av[8] = {a0.x,a0.y,a0.z,a0.w,a1.x,a1.y,a1.z,a1.w};
            float bv[8] = {b0.x,b0.y,b0.z,b0.w,b1.x,b1.y,b1.z,b1.w};
            #pragma unroll
            for (int i = 0; i < 8; i++)
                #pragma unroll
                for (int j = 0; j < 8; j++)
                    acc[i][j] = fmaf(av[i], bv[j], acc[i][j]);
        }
    }

    // max over this thread's 8 r-rows, then over the 16 ty groups via smem
    float cm[8];
    #pragma unroll
    for (int j = 0; j < 8; j++) {
        float v = acc[0][j];
        #pragma unroll
        for (int i = 1; i < 8; i++) v = fmaxf(v, acc[i][j]);
        cm[j] = v;
    }
    __syncthreads();
    #pragma unroll
    for (int j = 0; j < 8; j++) As[ty*132 + tx*8 + j] = cm[j];
    __syncthreads();
    if (t < 128) {
        float v = -1e30f;
        #pragma unroll
        for (int i = 0; i < 16; i++) v = fmaxf(v, As[i*132 + t]);
        out[((size_t)(b*LL + t)) * OC + 65 + m] = tanhf(v);
    }
}

// ============================================================================
extern "C" void kernel_launch(void* const* d_in, const int* in_sizes, int n_in,
                              void* d_out, int out_size)
{
    const float* reps_lt   = (const float*)d_in[0];
    // d_in[1], d_in[2] (h_lt_fw/bw) unused by the reference math
    const float* reps_rt   = (const float*)d_in[3];
    const float* h_rt_fw   = (const float*)d_in[4];
    const float* h_rt_bw   = (const float*)d_in[5];
    const float* k_full    = (const float*)d_in[6];
    const float* k_mpoolW  = (const float*)d_in[7];
    const float* attn_w1   = (const float*)d_in[8];
    const float* diag_w    = (const float*)d_in[9];
    const float* k_attW    = (const float*)d_in[10];
    const float* k_maxattW = (const float*)d_in[11];
    float* out = (float*)d_out;

    // dominant GEMM first
    k_mpool<<<dim3(M, B), 256>>>(reps_lt, reps_rt, k_mpoolW, out);

    // attentive path
    k_algt<<<(B*LL + B*LR) / 16, 256>>>(reps_lt, reps_rt, attn_w1, diag_w);
    k_att<<<dim3(LL/16, B), 256>>>(reps_rt);

    // max-attentive path
    k_nrt<<<B, 256>>>(reps_rt);
    k_idx<<<dim3(LL/16, B), 256>>>(reps_lt, reps_rt);

    // the three mp_match epilogues
    k_mp<<<B*LL, 256>>>(reps_lt, h_rt_fw, h_rt_bw, k_full,    out, 0,   0, reps_rt);
    k_mp<<<B*LL, 256>>>(reps_lt, h_rt_fw, h_rt_bw, k_attW,    out, 1, 129, reps_rt);
    k_mp<<<B*LL, 256>>>(reps_lt, h_rt_fw, h_rt_bw, k_maxattW, out, 2, 194, reps_rt);
}